// round 12
// baseline (speedup 1.0000x reference)
#include <cuda_runtime.h>
#include <cuda_bf16.h>
#include <cstdint>

#define N_NODES 50000
#define N_EDGES 1600000
#define C 128
#define E_TOT (N_EDGES + N_NODES)
#define NEG_SLOPE 0.2f
#define NEG_INF (-1e30f)
#define NBLK 49            // ceil(50000/1024)
#define NB 8               // nodes per block in GEMMs (50000 % 8 == 0)
#define GEMM_BLKS (N_NODES / NB)   // 6250
#define HIST_BLKS 2048

// -------- scratch (no device allocs allowed) --------
__device__ float g_h[(size_t)N_NODES * C];
__device__ float g_es[N_NODES];
__device__ float g_ed[N_NODES];
__device__ int   g_deg[N_NODES];
__device__ int   g_off[N_NODES + 1];
__device__ int   g_cursor[N_NODES];
__device__ int   g_adj[E_TOT];
__device__ int   g_bsum[NBLK + 1];

__device__ __forceinline__ float lrelu(float x) {
    return x > 0.f ? x : NEG_SLOPE * x;
}

// packed fp32x2 helpers (Blackwell FFMA2 — only reachable via PTX)
#define FFMA2(d, a, b, cc) \
    asm("fma.rn.f32x2 %0, %1, %2, %3;" : "=l"(d) : "l"(a), "l"(b), "l"(cc))
#define PACK2(d, lo, hi) \
    asm("mov.b64 %0, {%1, %2};" : "=l"(d) : "f"(lo), "f"(hi))
#define UNPACK2(lo, hi, s) \
    asm("mov.b64 {%0, %1}, %2;" : "=f"(lo), "=f"(hi) : "l"(s))

// ---- merged: GEMM blocks (NB=8, f32x2 packed math) + histogram ----
__global__ void k_gemm_hist(const float* __restrict__ x, const float* __restrict__ W,
                            const float* __restrict__ a_src, const float* __restrict__ a_dst,
                            const int* __restrict__ ei) {
    if (blockIdx.x >= GEMM_BLKS) {
        // -------- histogram part (independent of GEMM) --------
        int tid = (blockIdx.x - GEMM_BLKS) * 128 + threadIdx.x;
        int stride = HIST_BLKS * 128;
        for (int e = tid; e < E_TOT; e += stride) {
            int d = (e < N_EDGES) ? ei[N_EDGES + e] : (e - N_EDGES);
            atomicAdd(&g_deg[d], 1);
        }
        return;
    }
    // -------- GEMM part: h = x@W for 8 nodes, fused e_src/e_dst --------
    int nb = blockIdx.x * NB;
    int c = threadIdx.x;
    __shared__ float xs[C][NB];          // transposed: xs[k][i], rows 32B
#pragma unroll
    for (int i = 0; i < NB; i++)
        xs[c][i] = x[(size_t)(nb + i) * C + c];
    __syncthreads();

    unsigned long long p01 = 0ull, p23 = 0ull, p45 = 0ull, p67 = 0ull;
#pragma unroll 4
    for (int k = 0; k < C; k++) {
        float w = W[k * C + c];
        unsigned long long wp;
        PACK2(wp, w, w);
        ulonglong2 u0 = *(const ulonglong2*)&xs[k][0];   // LDS.128 broadcast: {x0x1, x2x3}
        ulonglong2 u1 = *(const ulonglong2*)&xs[k][4];   // {x4x5, x6x7}
        FFMA2(p01, u0.x, wp, p01);
        FFMA2(p23, u0.y, wp, p23);
        FFMA2(p45, u1.x, wp, p45);
        FFMA2(p67, u1.y, wp, p67);
    }
    float acc[NB];
    UNPACK2(acc[0], acc[1], p01);
    UNPACK2(acc[2], acc[3], p23);
    UNPACK2(acc[4], acc[5], p45);
    UNPACK2(acc[6], acc[7], p67);
#pragma unroll
    for (int i = 0; i < NB; i++)
        g_h[(size_t)(nb + i) * C + c] = acc[i];

    float as = a_src[c], ad = a_dst[c];
    __shared__ float rs[NB][4], rd[NB][4];
    int lane = c & 31, wp_ = c >> 5;
#pragma unroll
    for (int i = 0; i < NB; i++) {
        float ps = acc[i] * as;
        float pd = acc[i] * ad;
#pragma unroll
        for (int o = 16; o > 0; o >>= 1) {
            ps += __shfl_down_sync(0xffffffffu, ps, o);
            pd += __shfl_down_sync(0xffffffffu, pd, o);
        }
        if (lane == 0) { rs[i][wp_] = ps; rd[i][wp_] = pd; }
    }
    __syncthreads();
    if (c < NB) {
        g_es[nb + c] = rs[c][0] + rs[c][1] + rs[c][2] + rs[c][3];
        g_ed[nb + c] = rd[c][0] + rd[c][1] + rd[c][2] + rd[c][3];
    }
}

__global__ void k_zero() {
    int i = blockIdx.x * blockDim.x + threadIdx.x;
    if (i < N_NODES) g_deg[i] = 0;
}

// ---- scan phase 1: per-block exclusive scan + block sums ----
__global__ void k_scan1() {
    int b = blockIdx.x, tid = threadIdx.x;
    int idx = b * 1024 + tid;
    int v = (idx < N_NODES) ? g_deg[idx] : 0;
    int lane = tid & 31, wp = tid >> 5;
    int val = v;
#pragma unroll
    for (int o = 1; o < 32; o <<= 1) {
        int t = __shfl_up_sync(0xffffffffu, val, o);
        if (lane >= o) val += t;
    }
    __shared__ int wsum[32];
    if (lane == 31) wsum[wp] = val;
    __syncthreads();
    if (wp == 0) {
        int s = wsum[lane];
#pragma unroll
        for (int o = 1; o < 32; o <<= 1) {
            int t = __shfl_up_sync(0xffffffffu, s, o);
            if (lane >= o) s += t;
        }
        wsum[lane] = s;
    }
    __syncthreads();
    int incl = val + (wp ? wsum[wp - 1] : 0);
    if (idx < N_NODES) g_off[idx] = incl - v;        // local exclusive
    if (tid == 1023) g_bsum[b] = incl;               // raw block total
}

// ---- scan phase 3 (scan2 folded in): per-block carry + publish cursors ----
__global__ void k_scan3() {
    __shared__ int s_carry;
    int b = blockIdx.x, tid = threadIdx.x;
    if (tid == 0) {
        int acc = 0;
        for (int i = 0; i < b; i++) acc += g_bsum[i];
        s_carry = acc;
    }
    __syncthreads();
    int carry = s_carry;
    int idx = b * 1024 + tid;
    if (idx < N_NODES) {
        int o = g_off[idx] + carry;
        g_off[idx] = o;
        g_cursor[idx] = o;
    }
    if (b == NBLK - 1 && tid == 1023) {
        g_off[N_NODES] = carry + g_bsum[NBLK - 1];
    }
}

__global__ void k_fill(const int* __restrict__ ei) {
    int e = blockIdx.x * blockDim.x + threadIdx.x;
    if (e >= E_TOT) return;
    int s, d;
    if (e < N_EDGES) { s = ei[e]; d = ei[N_EDGES + e]; }
    else             { s = e - N_EDGES; d = s; }
    int pos = atomicAdd(&g_cursor[d], 1);
    g_adj[pos] = s;
}

// ---- fused softmax + aggregation: 1 warp per node, float4 lanes ----
__global__ void k_gather(const float* __restrict__ b_gat, float* __restrict__ zout) {
    int wp = threadIdx.x >> 5, lane = threadIdx.x & 31;
    int n = blockIdx.x * 4 + wp;
    int off = g_off[n];
    int deg = g_off[n + 1] - off;
    float edn = g_ed[n];

    float mt = NEG_INF, st = 0.f;
    for (int j = lane; j < deg; j += 32) {
        float l = lrelu(g_es[g_adj[off + j]] + edn);
        if (l > mt) { st *= __expf(mt - l); mt = l; }
        st += __expf(l - mt);
    }
#pragma unroll
    for (int o = 16; o > 0; o >>= 1) {
        float mo = __shfl_xor_sync(0xffffffffu, mt, o);
        float so = __shfl_xor_sync(0xffffffffu, st, o);
        float pm = fmaxf(mt, mo);
        float a = (mt > NEG_INF) ? st * __expf(mt - pm) : 0.f;
        float b = (mo > NEG_INF) ? so * __expf(mo - pm) : 0.f;
        mt = pm; st = a + b;
    }
    float inv = 1.f / st;

    float4 acc = make_float4(0.f, 0.f, 0.f, 0.f);
    for (int base = 0; base < deg; base += 32) {
        int j = base + lane;
        int sj = 0; float cj = 0.f;
        if (j < deg) {
            sj = g_adj[off + j];
            cj = __expf(lrelu(g_es[sj] + edn) - mt);
        }
        int lim = min(32, deg - base);
#pragma unroll 4
        for (int it = 0; it < lim; it++) {
            int s    = __shfl_sync(0xffffffffu, sj, it);
            float cf = __shfl_sync(0xffffffffu, cj, it);
            float4 v = *(const float4*)(g_h + (size_t)s * C + lane * 4);
            acc.x = fmaf(cf, v.x, acc.x);
            acc.y = fmaf(cf, v.y, acc.y);
            acc.z = fmaf(cf, v.z, acc.z);
            acc.w = fmaf(cf, v.w, acc.w);
        }
    }
    float4 bg = *(const float4*)(b_gat + lane * 4);
    float4 o4 = make_float4(acc.x * inv + bg.x, acc.y * inv + bg.y,
                            acc.z * inv + bg.z, acc.w * inv + bg.w);
    *(float4*)(zout + (size_t)n * C + lane * 4) = o4;
}

// ---- decode: recon = tanh(z @ Wd + bd), NB=8, f32x2 packed math ----
__global__ void k_decode(const float* __restrict__ Wd, const float* __restrict__ bd,
                         float* __restrict__ out) {
    int nb = blockIdx.x * NB;
    int c = threadIdx.x;
    __shared__ float zs[C][NB];          // transposed: zs[k][i]
    const float* zbase = out + (size_t)N_NODES * C;
#pragma unroll
    for (int i = 0; i < NB; i++)
        zs[c][i] = zbase[(size_t)(nb + i) * C + c];
    __syncthreads();

    float b = bd[c];
    unsigned long long p01, p23, p45, p67;
    PACK2(p01, b, b); p23 = p01; p45 = p01; p67 = p01;
#pragma unroll 4
    for (int k = 0; k < C; k++) {
        float w = Wd[k * C + c];
        unsigned long long wp;
        PACK2(wp, w, w);
        ulonglong2 u0 = *(const ulonglong2*)&zs[k][0];
        ulonglong2 u1 = *(const ulonglong2*)&zs[k][4];
        FFMA2(p01, u0.x, wp, p01);
        FFMA2(p23, u0.y, wp, p23);
        FFMA2(p45, u1.x, wp, p45);
        FFMA2(p67, u1.y, wp, p67);
    }
    float acc[NB];
    UNPACK2(acc[0], acc[1], p01);
    UNPACK2(acc[2], acc[3], p23);
    UNPACK2(acc[4], acc[5], p45);
    UNPACK2(acc[6], acc[7], p67);
#pragma unroll
    for (int i = 0; i < NB; i++)
        out[(size_t)(nb + i) * C + c] = tanhf(acc[i]);
}

extern "C" void kernel_launch(void* const* d_in, const int* in_sizes, int n_in,
                              void* d_out, int out_size) {
    const float* x     = (const float*)d_in[0];
    const int*   ei    = (const int*)d_in[1];     // int32 (JAX x64 off)
    const float* W     = (const float*)d_in[2];
    const float* a_src = (const float*)d_in[3];
    const float* a_dst = (const float*)d_in[4];
    const float* b_gat = (const float*)d_in[5];
    const float* Wd    = (const float*)d_in[6];
    const float* bd    = (const float*)d_in[7];
    float* out  = (float*)d_out;
    float* zout = out + (size_t)N_NODES * C;

    k_zero<<<(N_NODES + 255) / 256, 256>>>();
    k_gemm_hist<<<GEMM_BLKS + HIST_BLKS, C>>>(x, W, a_src, a_dst, ei);
    k_scan1<<<NBLK, 1024>>>();
    k_scan3<<<NBLK, 1024>>>();
    {
        int threads = 256;
        int eblocks = (E_TOT + threads - 1) / threads;
        k_fill<<<eblocks, threads>>>(ei);
    }
    k_gather<<<N_NODES / 4, 128>>>(b_gat, zout);
    k_decode<<<N_NODES / NB, C>>>(Wd, bd, out);
}

// round 13
// speedup vs baseline: 1.4316x; 1.4316x over previous
#include <cuda_runtime.h>
#include <cuda_bf16.h>
#include <cstdint>

#define N_NODES 50000
#define N_EDGES 1600000
#define C 128
#define E_TOT (N_EDGES + N_NODES)
#define NEG_SLOPE 0.2f
#define NEG_INF (-1e30f)
#define NBLK 49              // ceil(50000/1024)
#define TC_BLKS 782          // ceil(50000/64) 64-row GEMM tiles
#define HIST_BLKS 2048

// smem layout for TC GEMM (floats): As[64][132] then Ws[128][132]
#define AS_STRIDE 132
#define WS_OFF (64 * AS_STRIDE)
#define SMEM_FLOATS (WS_OFF + 128 * AS_STRIDE)
#define SMEM_BYTES (SMEM_FLOATS * 4)

// -------- scratch (no device allocs allowed) --------
__device__ float g_h[(size_t)N_NODES * C];
__device__ float g_es[N_NODES];
__device__ float g_ed[N_NODES];
__device__ int   g_deg[N_NODES];
__device__ int   g_off[N_NODES + 1];
__device__ int   g_cursor[N_NODES];
__device__ int   g_adj[E_TOT];
__device__ int   g_bsum[NBLK + 1];

__device__ __forceinline__ float lrelu(float x) {
    return x > 0.f ? x : NEG_SLOPE * x;
}
__device__ __forceinline__ unsigned tf32_of(float f) {
    unsigned u;
    asm("cvt.rna.tf32.f32 %0, %1;" : "=r"(u) : "f"(f));
    return u;
}
#define MMA_TF32(c0,c1,c2,c3,a0,a1,a2,a3,b0,b1) \
    asm("mma.sync.aligned.m16n8k8.row.col.f32.tf32.tf32.f32 " \
        "{%0,%1,%2,%3}, {%4,%5,%6,%7}, {%8,%9}, {%0,%1,%2,%3};" \
        : "+f"(c0), "+f"(c1), "+f"(c2), "+f"(c3) \
        : "r"(a0), "r"(a1), "r"(a2), "r"(a3), "r"(b0), "r"(b1))

// ---- merged: tf32 tensor-core GEMM (h=x@W, fused e_src/e_dst) + histogram ----
__global__ void __launch_bounds__(128) k_gemm_hist(
        const float* __restrict__ x, const float* __restrict__ W,
        const float* __restrict__ a_src, const float* __restrict__ a_dst,
        const int* __restrict__ ei) {
    if (blockIdx.x >= TC_BLKS) {
        int tid = (blockIdx.x - TC_BLKS) * 128 + threadIdx.x;
        int stride = HIST_BLKS * 128;
        for (int e = tid; e < E_TOT; e += stride) {
            int d = (e < N_EDGES) ? ei[N_EDGES + e] : (e - N_EDGES);
            atomicAdd(&g_deg[d], 1);
        }
        return;
    }
    extern __shared__ float sm[];
    float* As = sm;                 // As[r][k], stride AS_STRIDE, tf32 bits
    float* Ws = sm + WS_OFF;        // Ws[k][n], stride AS_STRIDE, tf32 bits
    int tid = threadIdx.x;
    int m0 = blockIdx.x * 64;

    // stage x tile (guarded, tf32-converted)
    for (int i = tid; i < 64 * C; i += 128) {
        int r = i >> 7, k = i & 127;
        int row = m0 + r;
        float v = (row < N_NODES) ? x[(size_t)row * C + k] : 0.f;
        As[r * AS_STRIDE + k] = __uint_as_float(tf32_of(v));
    }
    // stage W (tf32-converted)
    for (int i = tid; i < C * C; i += 128) {
        int k = i >> 7, n = i & 127;
        Ws[k * AS_STRIDE + n] = __uint_as_float(tf32_of(W[k * C + n]));
    }
    __syncthreads();

    int w = tid >> 5, lane = tid & 31;
    int g = lane >> 2, q = lane & 3;
    float c0[16], c1[16], c2[16], c3[16];
#pragma unroll
    for (int j = 0; j < 16; j++) { c0[j] = 0.f; c1[j] = 0.f; c2[j] = 0.f; c3[j] = 0.f; }

    const float* Ar0 = As + (w * 16 + g) * AS_STRIDE;
    const float* Ar1 = Ar0 + 8 * AS_STRIDE;
    for (int ks = 0; ks < 16; ks++) {
        int k0 = ks * 8;
        unsigned a0 = __float_as_uint(Ar0[k0 + q]);
        unsigned a1 = __float_as_uint(Ar1[k0 + q]);
        unsigned a2 = __float_as_uint(Ar0[k0 + q + 4]);
        unsigned a3 = __float_as_uint(Ar1[k0 + q + 4]);
        const float* Wk0 = Ws + (k0 + q) * AS_STRIDE + g;
        const float* Wk1 = Wk0 + 4 * AS_STRIDE;
#pragma unroll
        for (int j = 0; j < 16; j++) {
            unsigned b0 = __float_as_uint(Wk0[j * 8]);
            unsigned b1 = __float_as_uint(Wk1[j * 8]);
            MMA_TF32(c0[j], c1[j], c2[j], c3[j], a0, a1, a2, a3, b0, b1);
        }
    }

    // epilogue: store h rows + fused attention dots
    int row0 = m0 + w * 16 + g;
    int row1 = row0 + 8;
    float ps0 = 0.f, pd0 = 0.f, ps1 = 0.f, pd1 = 0.f;
#pragma unroll
    for (int j = 0; j < 16; j++) {
        int col = j * 8 + 2 * q;
        float2 av = *(const float2*)(a_src + col);
        float2 dv = *(const float2*)(a_dst + col);
        ps0 += c0[j] * av.x + c1[j] * av.y;
        pd0 += c0[j] * dv.x + c1[j] * dv.y;
        ps1 += c2[j] * av.x + c3[j] * av.y;
        pd1 += c2[j] * dv.x + c3[j] * dv.y;
        if (row0 < N_NODES)
            *(float2*)(g_h + (size_t)row0 * C + col) = make_float2(c0[j], c1[j]);
        if (row1 < N_NODES)
            *(float2*)(g_h + (size_t)row1 * C + col) = make_float2(c2[j], c3[j]);
    }
    // reduce over the 4 lanes of the quad (same g, q=0..3)
#pragma unroll
    for (int o = 1; o < 4; o <<= 1) {
        ps0 += __shfl_xor_sync(0xffffffffu, ps0, o);
        pd0 += __shfl_xor_sync(0xffffffffu, pd0, o);
        ps1 += __shfl_xor_sync(0xffffffffu, ps1, o);
        pd1 += __shfl_xor_sync(0xffffffffu, pd1, o);
    }
    if (q == 0) {
        if (row0 < N_NODES) { g_es[row0] = ps0; g_ed[row0] = pd0; }
        if (row1 < N_NODES) { g_es[row1] = ps1; g_ed[row1] = pd1; }
    }
}

__global__ void k_zero() {
    int i = blockIdx.x * blockDim.x + threadIdx.x;
    if (i < N_NODES) g_deg[i] = 0;
}

// ---- scan phase 1 ----
__global__ void k_scan1() {
    int b = blockIdx.x, tid = threadIdx.x;
    int idx = b * 1024 + tid;
    int v = (idx < N_NODES) ? g_deg[idx] : 0;
    int lane = tid & 31, wp = tid >> 5;
    int val = v;
#pragma unroll
    for (int o = 1; o < 32; o <<= 1) {
        int t = __shfl_up_sync(0xffffffffu, val, o);
        if (lane >= o) val += t;
    }
    __shared__ int wsum[32];
    if (lane == 31) wsum[wp] = val;
    __syncthreads();
    if (wp == 0) {
        int s = wsum[lane];
#pragma unroll
        for (int o = 1; o < 32; o <<= 1) {
            int t = __shfl_up_sync(0xffffffffu, s, o);
            if (lane >= o) s += t;
        }
        wsum[lane] = s;
    }
    __syncthreads();
    int incl = val + (wp ? wsum[wp - 1] : 0);
    if (idx < N_NODES) g_off[idx] = incl - v;
    if (tid == 1023) g_bsum[b] = incl;
}

// ---- scan phase 3 (carry + cursors) ----
__global__ void k_scan3() {
    __shared__ int s_carry;
    int b = blockIdx.x, tid = threadIdx.x;
    if (tid == 0) {
        int acc = 0;
        for (int i = 0; i < b; i++) acc += g_bsum[i];
        s_carry = acc;
    }
    __syncthreads();
    int carry = s_carry;
    int idx = b * 1024 + tid;
    if (idx < N_NODES) {
        int o = g_off[idx] + carry;
        g_off[idx] = o;
        g_cursor[idx] = o;
    }
    if (b == NBLK - 1 && tid == 1023)
        g_off[N_NODES] = carry + g_bsum[NBLK - 1];
}

__global__ void k_fill(const int* __restrict__ ei) {
    int e = blockIdx.x * blockDim.x + threadIdx.x;
    if (e >= E_TOT) return;
    int s, d;
    if (e < N_EDGES) { s = ei[e]; d = ei[N_EDGES + e]; }
    else             { s = e - N_EDGES; d = s; }
    int pos = atomicAdd(&g_cursor[d], 1);
    g_adj[pos] = s;
}

// ---- fused softmax + aggregation: 1 warp per node, float4 lanes ----
__global__ void k_gather(const float* __restrict__ b_gat, float* __restrict__ zout) {
    int wp = threadIdx.x >> 5, lane = threadIdx.x & 31;
    int n = blockIdx.x * 4 + wp;
    int off = g_off[n];
    int deg = g_off[n + 1] - off;
    float edn = g_ed[n];

    float mt = NEG_INF, st = 0.f;
    for (int j = lane; j < deg; j += 32) {
        float l = lrelu(g_es[g_adj[off + j]] + edn);
        if (l > mt) { st *= __expf(mt - l); mt = l; }
        st += __expf(l - mt);
    }
#pragma unroll
    for (int o = 16; o > 0; o >>= 1) {
        float mo = __shfl_xor_sync(0xffffffffu, mt, o);
        float so = __shfl_xor_sync(0xffffffffu, st, o);
        float pm = fmaxf(mt, mo);
        float a = (mt > NEG_INF) ? st * __expf(mt - pm) : 0.f;
        float b = (mo > NEG_INF) ? so * __expf(mo - pm) : 0.f;
        mt = pm; st = a + b;
    }
    float inv = 1.f / st;

    float4 acc = make_float4(0.f, 0.f, 0.f, 0.f);
    for (int base = 0; base < deg; base += 32) {
        int j = base + lane;
        int sj = 0; float cj = 0.f;
        if (j < deg) {
            sj = g_adj[off + j];
            cj = __expf(lrelu(g_es[sj] + edn) - mt);
        }
        int lim = min(32, deg - base);
#pragma unroll 4
        for (int it = 0; it < lim; it++) {
            int s    = __shfl_sync(0xffffffffu, sj, it);
            float cf = __shfl_sync(0xffffffffu, cj, it);
            float4 v = *(const float4*)(g_h + (size_t)s * C + lane * 4);
            acc.x = fmaf(cf, v.x, acc.x);
            acc.y = fmaf(cf, v.y, acc.y);
            acc.z = fmaf(cf, v.z, acc.z);
            acc.w = fmaf(cf, v.w, acc.w);
        }
    }
    float4 bg = *(const float4*)(b_gat + lane * 4);
    float4 o4 = make_float4(acc.x * inv + bg.x, acc.y * inv + bg.y,
                            acc.z * inv + bg.z, acc.w * inv + bg.w);
    *(float4*)(zout + (size_t)n * C + lane * 4) = o4;
}

// ---- decode: recon = tanh(z @ Wd + bd), tf32 tensor-core GEMM ----
__global__ void __launch_bounds__(128) k_decode(
        const float* __restrict__ Wd, const float* __restrict__ bd,
        float* __restrict__ out) {
    extern __shared__ float sm[];
    float* As = sm;
    float* Ws = sm + WS_OFF;
    int tid = threadIdx.x;
    int m0 = blockIdx.x * 64;
    const float* z = out + (size_t)N_NODES * C;

    for (int i = tid; i < 64 * C; i += 128) {
        int r = i >> 7, k = i & 127;
        int row = m0 + r;
        float v = (row < N_NODES) ? z[(size_t)row * C + k] : 0.f;
        As[r * AS_STRIDE + k] = __uint_as_float(tf32_of(v));
    }
    for (int i = tid; i < C * C; i += 128) {
        int k = i >> 7, n = i & 127;
        Ws[k * AS_STRIDE + n] = __uint_as_float(tf32_of(Wd[k * C + n]));
    }
    __syncthreads();

    int w = tid >> 5, lane = tid & 31;
    int g = lane >> 2, q = lane & 3;
    float c0[16], c1[16], c2[16], c3[16];
#pragma unroll
    for (int j = 0; j < 16; j++) { c0[j] = 0.f; c1[j] = 0.f; c2[j] = 0.f; c3[j] = 0.f; }

    const float* Ar0 = As + (w * 16 + g) * AS_STRIDE;
    const float* Ar1 = Ar0 + 8 * AS_STRIDE;
    for (int ks = 0; ks < 16; ks++) {
        int k0 = ks * 8;
        unsigned a0 = __float_as_uint(Ar0[k0 + q]);
        unsigned a1 = __float_as_uint(Ar1[k0 + q]);
        unsigned a2 = __float_as_uint(Ar0[k0 + q + 4]);
        unsigned a3 = __float_as_uint(Ar1[k0 + q + 4]);
        const float* Wk0 = Ws + (k0 + q) * AS_STRIDE + g;
        const float* Wk1 = Wk0 + 4 * AS_STRIDE;
#pragma unroll
        for (int j = 0; j < 16; j++) {
            unsigned b0 = __float_as_uint(Wk0[j * 8]);
            unsigned b1 = __float_as_uint(Wk1[j * 8]);
            MMA_TF32(c0[j], c1[j], c2[j], c3[j], a0, a1, a2, a3, b0, b1);
        }
    }

    int row0 = m0 + w * 16 + g;
    int row1 = row0 + 8;
#pragma unroll
    for (int j = 0; j < 16; j++) {
        int col = j * 8 + 2 * q;
        float2 bv = *(const float2*)(bd + col);
        if (row0 < N_NODES)
            *(float2*)(out + (size_t)row0 * C + col) =
                make_float2(tanhf(c0[j] + bv.x), tanhf(c1[j] + bv.y));
        if (row1 < N_NODES)
            *(float2*)(out + (size_t)row1 * C + col) =
                make_float2(tanhf(c2[j] + bv.x), tanhf(c3[j] + bv.y));
    }
}

extern "C" void kernel_launch(void* const* d_in, const int* in_sizes, int n_in,
                              void* d_out, int out_size) {
    const float* x     = (const float*)d_in[0];
    const int*   ei    = (const int*)d_in[1];     // int32 (JAX x64 off)
    const float* W     = (const float*)d_in[2];
    const float* a_src = (const float*)d_in[3];
    const float* a_dst = (const float*)d_in[4];
    const float* b_gat = (const float*)d_in[5];
    const float* Wd    = (const float*)d_in[6];
    const float* bd    = (const float*)d_in[7];
    float* out  = (float*)d_out;
    float* zout = out + (size_t)N_NODES * C;

    cudaFuncSetAttribute(k_gemm_hist, cudaFuncAttributeMaxDynamicSharedMemorySize, SMEM_BYTES);
    cudaFuncSetAttribute(k_decode,   cudaFuncAttributeMaxDynamicSharedMemorySize, SMEM_BYTES);

    k_zero<<<(N_NODES + 255) / 256, 256>>>();
    k_gemm_hist<<<TC_BLKS + HIST_BLKS, 128, SMEM_BYTES>>>(x, W, a_src, a_dst, ei);
    k_scan1<<<NBLK, 1024>>>();
    k_scan3<<<NBLK, 1024>>>();
    {
        int threads = 256;
        int eblocks = (E_TOT + threads - 1) / threads;
        k_fill<<<eblocks, threads>>>(ei);
    }
    k_gather<<<N_NODES / 4, 128>>>(b_gat, zout);
    k_decode<<<TC_BLKS, 128, SMEM_BYTES>>>(Wd, bd, out);
}

// round 14
// speedup vs baseline: 1.5189x; 1.0610x over previous
#include <cuda_runtime.h>
#include <cuda_bf16.h>
#include <cstdint>

#define N_NODES 50000
#define N_EDGES 1600000
#define C 128
#define E_TOT (N_EDGES + N_NODES)
#define NEG_SLOPE 0.2f
#define NEG_INF (-1e30f)
#define NBLK 49              // ceil(50000/1024)
#define NB 8                 // nodes per block in gemm1
#define GEMM_BLKS (N_NODES / NB)   // 6250
#define HIST_BLKS 2048
#define N_TILES 782          // ceil(50000/64)
#define DEC_BLKS 148
#define DEC_THREADS 256
#define AS_STRIDE 132
#define DEC_SMEM ((128 + 64) * AS_STRIDE * 4)

// -------- scratch (no device allocs allowed) --------
__device__ float g_h[(size_t)N_NODES * C];
__device__ float g_es[N_NODES];
__device__ float g_ed[N_NODES];
__device__ int   g_deg[N_NODES];
__device__ int   g_off[N_NODES + 1];
__device__ int   g_cursor[N_NODES];
__device__ int   g_adj[E_TOT];
__device__ int   g_bsumv[NBLK];
__device__ int   g_bflag[NBLK];

__device__ __forceinline__ float lrelu(float x) {
    return x > 0.f ? x : NEG_SLOPE * x;
}
__device__ __forceinline__ unsigned tf32_of(float f) {
    unsigned u;
    asm("cvt.rna.tf32.f32 %0, %1;" : "=r"(u) : "f"(f));
    return u;
}
#define MMA_TF32(c0,c1,c2,c3,a0,a1,a2,a3,b0,b1) \
    asm("mma.sync.aligned.m16n8k8.row.col.f32.tf32.tf32.f32 " \
        "{%0,%1,%2,%3}, {%4,%5,%6,%7}, {%8,%9}, {%0,%1,%2,%3};" \
        : "+f"(c0), "+f"(c1), "+f"(c2), "+f"(c3) \
        : "r"(a0), "r"(a1), "r"(a2), "r"(a3), "r"(b0), "r"(b1))

// ---- merged: FFMA GEMM (R10 body, off critical path) + histogram ----
__global__ void k_gemm_hist(const float* __restrict__ x, const float* __restrict__ W,
                            const float* __restrict__ a_src, const float* __restrict__ a_dst,
                            const int* __restrict__ ei) {
    if (blockIdx.x >= GEMM_BLKS) {
        int tid = (blockIdx.x - GEMM_BLKS) * 128 + threadIdx.x;
        int stride = HIST_BLKS * 128;
        for (int e = tid; e < E_TOT; e += stride) {
            int d = (e < N_EDGES) ? ei[N_EDGES + e] : (e - N_EDGES);
            atomicAdd(&g_deg[d], 1);
        }
        return;
    }
    int nb = blockIdx.x * NB;
    int c = threadIdx.x;
    __shared__ float xs[C][NB];          // transposed: xs[k][i]
#pragma unroll
    for (int i = 0; i < NB; i++)
        xs[c][i] = x[(size_t)(nb + i) * C + c];
    __syncthreads();
    float acc[NB];
#pragma unroll
    for (int i = 0; i < NB; i++) acc[i] = 0.f;
#pragma unroll 4
    for (int k = 0; k < C; k++) {
        float w = W[k * C + c];
        const float4 a0 = *(const float4*)&xs[k][0];
        const float4 a1 = *(const float4*)&xs[k][4];
        acc[0] = fmaf(a0.x, w, acc[0]);  acc[1] = fmaf(a0.y, w, acc[1]);
        acc[2] = fmaf(a0.z, w, acc[2]);  acc[3] = fmaf(a0.w, w, acc[3]);
        acc[4] = fmaf(a1.x, w, acc[4]);  acc[5] = fmaf(a1.y, w, acc[5]);
        acc[6] = fmaf(a1.z, w, acc[6]);  acc[7] = fmaf(a1.w, w, acc[7]);
    }
#pragma unroll
    for (int i = 0; i < NB; i++)
        g_h[(size_t)(nb + i) * C + c] = acc[i];

    float as = a_src[c], ad = a_dst[c];
    __shared__ float rs[NB][4], rd[NB][4];
    int lane = c & 31, wp = c >> 5;
#pragma unroll
    for (int i = 0; i < NB; i++) {
        float ps = acc[i] * as;
        float pd = acc[i] * ad;
#pragma unroll
        for (int o = 16; o > 0; o >>= 1) {
            ps += __shfl_down_sync(0xffffffffu, ps, o);
            pd += __shfl_down_sync(0xffffffffu, pd, o);
        }
        if (lane == 0) { rs[i][wp] = ps; rd[i][wp] = pd; }
    }
    __syncthreads();
    if (c < NB) {
        g_es[nb + c] = rs[c][0] + rs[c][1] + rs[c][2] + rs[c][3];
        g_ed[nb + c] = rd[c][0] + rd[c][1] + rd[c][2] + rd[c][3];
    }
}

__global__ void k_zero() {
    int i = blockIdx.x * blockDim.x + threadIdx.x;
    if (i < N_NODES) g_deg[i] = 0;
    if (i < NBLK) g_bflag[i] = 0;
}

// ---- fused scan (scan1 + carry via publish/poll; 49 blocks all resident) ----
__global__ void k_scan_fused() {
    int b = blockIdx.x, tid = threadIdx.x;
    int idx = b * 1024 + tid;
    int v = (idx < N_NODES) ? g_deg[idx] : 0;
    int lane = tid & 31, wp = tid >> 5;
    int val = v;
#pragma unroll
    for (int o = 1; o < 32; o <<= 1) {
        int t = __shfl_up_sync(0xffffffffu, val, o);
        if (lane >= o) val += t;
    }
    __shared__ int wsum[32];
    if (lane == 31) wsum[wp] = val;
    __syncthreads();
    if (wp == 0) {
        int s = wsum[lane];
#pragma unroll
        for (int o = 1; o < 32; o <<= 1) {
            int t = __shfl_up_sync(0xffffffffu, s, o);
            if (lane >= o) s += t;
        }
        wsum[lane] = s;
    }
    __syncthreads();
    int total = wsum[31];
    int incl = val + (wp ? wsum[wp - 1] : 0);

    // publish this block's total
    if (tid == 0) {
        g_bsumv[b] = total;
        __threadfence();
        *(volatile int*)&g_bflag[b] = 1;
    }
    // gather carries from prior blocks (parallel poll, b <= 48)
    __shared__ int sv[64];
    __shared__ int s_carry;
    if (tid < b) {
        while (*(volatile int*)&g_bflag[tid] == 0) { }
        sv[tid] = *(volatile int*)&g_bsumv[tid];
    }
    __syncthreads();
    if (tid == 0) {
        int acc = 0;
        for (int i = 0; i < b; i++) acc += sv[i];
        s_carry = acc;
    }
    __syncthreads();
    int carry = s_carry;
    if (idx < N_NODES) {
        int o = (incl - v) + carry;
        g_off[idx] = o;
        g_cursor[idx] = o;
    }
    if (b == NBLK - 1 && tid == 1023)
        g_off[N_NODES] = carry + total;
}

__global__ void k_fill(const int* __restrict__ ei) {
    int e = blockIdx.x * blockDim.x + threadIdx.x;
    if (e >= E_TOT) return;
    int s, d;
    if (e < N_EDGES) { s = ei[e]; d = ei[N_EDGES + e]; }
    else             { s = e - N_EDGES; d = s; }
    int pos = atomicAdd(&g_cursor[d], 1);
    g_adj[pos] = s;
}

// ---- fused softmax + aggregation: 1 warp per node, float4 lanes ----
__global__ void k_gather(const float* __restrict__ b_gat, float* __restrict__ zout) {
    int wp = threadIdx.x >> 5, lane = threadIdx.x & 31;
    int n = blockIdx.x * 4 + wp;
    int off = g_off[n];
    int deg = g_off[n + 1] - off;
    float edn = g_ed[n];

    float mt = NEG_INF, st = 0.f;
    for (int j = lane; j < deg; j += 32) {
        float l = lrelu(g_es[g_adj[off + j]] + edn);
        if (l > mt) { st *= __expf(mt - l); mt = l; }
        st += __expf(l - mt);
    }
#pragma unroll
    for (int o = 16; o > 0; o >>= 1) {
        float mo = __shfl_xor_sync(0xffffffffu, mt, o);
        float so = __shfl_xor_sync(0xffffffffu, st, o);
        float pm = fmaxf(mt, mo);
        float a = (mt > NEG_INF) ? st * __expf(mt - pm) : 0.f;
        float b = (mo > NEG_INF) ? so * __expf(mo - pm) : 0.f;
        mt = pm; st = a + b;
    }
    float inv = 1.f / st;

    float4 acc = make_float4(0.f, 0.f, 0.f, 0.f);
    for (int base = 0; base < deg; base += 32) {
        int j = base + lane;
        int sj = 0; float cj = 0.f;
        if (j < deg) {
            sj = g_adj[off + j];
            cj = __expf(lrelu(g_es[sj] + edn) - mt);
        }
        int lim = min(32, deg - base);
#pragma unroll 4
        for (int it = 0; it < lim; it++) {
            int s    = __shfl_sync(0xffffffffu, sj, it);
            float cf = __shfl_sync(0xffffffffu, cj, it);
            float4 v = *(const float4*)(g_h + (size_t)s * C + lane * 4);
            acc.x = fmaf(cf, v.x, acc.x);
            acc.y = fmaf(cf, v.y, acc.y);
            acc.z = fmaf(cf, v.z, acc.z);
            acc.w = fmaf(cf, v.w, acc.w);
        }
    }
    float4 bg = *(const float4*)(b_gat + lane * 4);
    float4 o4 = make_float4(acc.x * inv + bg.x, acc.y * inv + bg.y,
                            acc.z * inv + bg.z, acc.w * inv + bg.w);
    *(float4*)(zout + (size_t)n * C + lane * 4) = o4;
}

// ---- persistent TC decode: recon = tanh(z @ Wd + bd) ----
// 148 blocks x 256 threads. Wd staged to smem ONCE per block; ~5 tiles each.
// 8 warps: rows 16*(w&3).. , N-half 64*(w>>2).
__global__ void __launch_bounds__(DEC_THREADS) k_decode(
        const float* __restrict__ Wd, const float* __restrict__ bd,
        float* __restrict__ out) {
    extern __shared__ float sm[];
    float* Ws = sm;                       // [128][AS_STRIDE]
    float* Zs = sm + 128 * AS_STRIDE;     // [64][AS_STRIDE]
    int tid = threadIdx.x;

    for (int i = tid; i < C * C; i += DEC_THREADS) {
        int k = i >> 7, n = i & 127;
        Ws[k * AS_STRIDE + n] = __uint_as_float(tf32_of(Wd[k * C + n]));
    }

    const float* z = out + (size_t)N_NODES * C;
    int w = tid >> 5, lane = tid & 31;
    int g = lane >> 2, q = lane & 3;
    int wr = w & 3;
    int wn = (w >> 2) * 64;

    for (int t = blockIdx.x; t < N_TILES; t += DEC_BLKS) {
        int m0 = t * 64;
        __syncthreads();   // Ws ready (1st iter); Zs reads done (later iters)
        for (int i = tid; i < 64 * C; i += DEC_THREADS) {
            int r = i >> 7, k = i & 127;
            int row = m0 + r;
            float v = (row < N_NODES) ? z[(size_t)row * C + k] : 0.f;
            Zs[r * AS_STRIDE + k] = __uint_as_float(tf32_of(v));
        }
        __syncthreads();

        float c0[8], c1[8], c2[8], c3[8];
#pragma unroll
        for (int j = 0; j < 8; j++) { c0[j] = 0.f; c1[j] = 0.f; c2[j] = 0.f; c3[j] = 0.f; }

        const float* Ar0 = Zs + (wr * 16 + g) * AS_STRIDE;
        const float* Ar1 = Ar0 + 8 * AS_STRIDE;
#pragma unroll 4
        for (int ks = 0; ks < 16; ks++) {
            int k0 = ks * 8;
            unsigned a0 = __float_as_uint(Ar0[k0 + q]);
            unsigned a1 = __float_as_uint(Ar1[k0 + q]);
            unsigned a2 = __float_as_uint(Ar0[k0 + q + 4]);
            unsigned a3 = __float_as_uint(Ar1[k0 + q + 4]);
            const float* Wk0 = Ws + (k0 + q) * AS_STRIDE + wn + g;
            const float* Wk1 = Wk0 + 4 * AS_STRIDE;
#pragma unroll
            for (int j = 0; j < 8; j++) {
                unsigned b0 = __float_as_uint(Wk0[j * 8]);
                unsigned b1 = __float_as_uint(Wk1[j * 8]);
                MMA_TF32(c0[j], c1[j], c2[j], c3[j], a0, a1, a2, a3, b0, b1);
            }
        }

        int row0 = m0 + wr * 16 + g;
        int row1 = row0 + 8;
#pragma unroll
        for (int j = 0; j < 8; j++) {
            int col = wn + j * 8 + 2 * q;
            float2 bv = *(const float2*)(bd + col);
            if (row0 < N_NODES)
                *(float2*)(out + (size_t)row0 * C + col) =
                    make_float2(tanhf(c0[j] + bv.x), tanhf(c1[j] + bv.y));
            if (row1 < N_NODES)
                *(float2*)(out + (size_t)row1 * C + col) =
                    make_float2(tanhf(c2[j] + bv.x), tanhf(c3[j] + bv.y));
        }
    }
}

extern "C" void kernel_launch(void* const* d_in, const int* in_sizes, int n_in,
                              void* d_out, int out_size) {
    const float* x     = (const float*)d_in[0];
    const int*   ei    = (const int*)d_in[1];     // int32 (JAX x64 off)
    const float* W     = (const float*)d_in[2];
    const float* a_src = (const float*)d_in[3];
    const float* a_dst = (const float*)d_in[4];
    const float* b_gat = (const float*)d_in[5];
    const float* Wd    = (const float*)d_in[6];
    const float* bd    = (const float*)d_in[7];
    float* out  = (float*)d_out;
    float* zout = out + (size_t)N_NODES * C;

    cudaFuncSetAttribute(k_decode, cudaFuncAttributeMaxDynamicSharedMemorySize, DEC_SMEM);

    k_zero<<<(N_NODES + 255) / 256, 256>>>();
    k_gemm_hist<<<GEMM_BLKS + HIST_BLKS, C>>>(x, W, a_src, a_dst, ei);
    k_scan_fused<<<NBLK, 1024>>>();
    {
        int threads = 256;
        int eblocks = (E_TOT + threads - 1) / threads;
        k_fill<<<eblocks, threads>>>(ei);
    }
    k_gather<<<N_NODES / 4, 128>>>(b_gat, zout);
    k_decode<<<DEC_BLKS, DEC_THREADS, DEC_SMEM>>>(Wd, bd, out);
}

// round 15
// speedup vs baseline: 1.5827x; 1.0420x over previous
#include <cuda_runtime.h>
#include <cuda_fp16.h>
#include <cstdint>

#define N_NODES 50000
#define N_EDGES 1600000
#define C 128
#define CH2 (C / 2)
#define E_TOT (N_EDGES + N_NODES)
#define NEG_SLOPE 0.2f
#define NEG_INF (-1e30f)
#define NBLK 49              // ceil(50000/1024)
#define NB 8                 // nodes per block in gemm1
#define GEMM_BLKS (N_NODES / NB)   // 6250
#define FILL_BLKS 3223       // ceil(E_TOT/512)
#define N_TILES 782          // ceil(50000/64)
#define DEC_BLKS 148
#define DEC_THREADS 256
#define AS_STRIDE 132
#define DEC_SMEM ((128 + 64) * AS_STRIDE * 4)

// -------- scratch (no device allocs allowed) --------
__device__ __half2 g_h16[(size_t)N_NODES * CH2];   // h in fp16 (gather feed)
__device__ float g_es[N_NODES];
__device__ float g_ed[N_NODES];
__device__ int   g_deg[N_NODES];
__device__ int   g_off[N_NODES + 1];
__device__ int   g_cursor[N_NODES];
__device__ int   g_adj[E_TOT];
__device__ int   g_bsumv[NBLK];
__device__ int   g_bflag[NBLK];

__device__ __forceinline__ float lrelu(float x) {
    return x > 0.f ? x : NEG_SLOPE * x;
}
__device__ __forceinline__ unsigned tf32_of(float f) {
    unsigned u;
    asm("cvt.rna.tf32.f32 %0, %1;" : "=r"(u) : "f"(f));
    return u;
}
#define MMA_TF32(c0,c1,c2,c3,a0,a1,a2,a3,b0,b1) \
    asm("mma.sync.aligned.m16n8k8.row.col.f32.tf32.tf32.f32 " \
        "{%0,%1,%2,%3}, {%4,%5,%6,%7}, {%8,%9}, {%0,%1,%2,%3};" \
        : "+f"(c0), "+f"(c1), "+f"(c2), "+f"(c3) \
        : "r"(a0), "r"(a1), "r"(a2), "r"(a3), "r"(b0), "r"(b1))

// ---- zero degree histogram + scan flags ----
__global__ void k_zero() {
    int i = blockIdx.x * blockDim.x + threadIdx.x;
    if (i < N_NODES) g_deg[i] = 0;
    if (i < NBLK) g_bflag[i] = 0;
}

// ---- standalone histogram (first in chain) ----
__global__ void k_hist(const int* __restrict__ ei) {
    int e = blockIdx.x * blockDim.x + threadIdx.x;
    if (e >= E_TOT) return;
    int d = (e < N_EDGES) ? ei[N_EDGES + e] : (e - N_EDGES);
    atomicAdd(&g_deg[d], 1);
}

// ---- fused scan (publish/poll; 49 blocks all wave-1 resident) ----
__global__ void k_scan_fused() {
    int b = blockIdx.x, tid = threadIdx.x;
    int idx = b * 1024 + tid;
    int v = (idx < N_NODES) ? g_deg[idx] : 0;
    int lane = tid & 31, wp = tid >> 5;
    int val = v;
#pragma unroll
    for (int o = 1; o < 32; o <<= 1) {
        int t = __shfl_up_sync(0xffffffffu, val, o);
        if (lane >= o) val += t;
    }
    __shared__ int wsum[32];
    if (lane == 31) wsum[wp] = val;
    __syncthreads();
    if (wp == 0) {
        int s = wsum[lane];
#pragma unroll
        for (int o = 1; o < 32; o <<= 1) {
            int t = __shfl_up_sync(0xffffffffu, s, o);
            if (lane >= o) s += t;
        }
        wsum[lane] = s;
    }
    __syncthreads();
    int total = wsum[31];
    int incl = val + (wp ? wsum[wp - 1] : 0);

    if (tid == 0) {
        g_bsumv[b] = total;
        __threadfence();
        *(volatile int*)&g_bflag[b] = 1;
    }
    __shared__ int sv[64];
    __shared__ int s_carry;
    if (tid < b) {
        while (*(volatile int*)&g_bflag[tid] == 0) { }
        sv[tid] = *(volatile int*)&g_bsumv[tid];
    }
    __syncthreads();
    if (tid == 0) {
        int acc = 0;
        for (int i = 0; i < b; i++) acc += sv[i];
        s_carry = acc;
    }
    __syncthreads();
    int carry = s_carry;
    if (idx < N_NODES) {
        int o = (incl - v) + carry;
        g_off[idx] = o;
        g_cursor[idx] = o;
    }
    if (b == NBLK - 1 && tid == 1023)
        g_off[N_NODES] = carry + total;
}

// ---- merged: FFMA GEMM (h=x@W + es/ed, fp16 h store) + CSR fill ----
__global__ void k_gemm_fill(const float* __restrict__ x, const float* __restrict__ W,
                            const float* __restrict__ a_src, const float* __restrict__ a_dst,
                            const int* __restrict__ ei) {
    if (blockIdx.x >= GEMM_BLKS) {
        // -------- fill part (needs cursors from scan; independent of GEMM) ----
        int tid = (blockIdx.x - GEMM_BLKS) * 128 + threadIdx.x;
        int stride = FILL_BLKS * 128;
        for (int e = tid; e < E_TOT; e += stride) {
            int s, d;
            if (e < N_EDGES) { s = ei[e]; d = ei[N_EDGES + e]; }
            else             { s = e - N_EDGES; d = s; }
            int pos = atomicAdd(&g_cursor[d], 1);
            g_adj[pos] = s;
        }
        return;
    }
    // -------- GEMM part --------
    int nb = blockIdx.x * NB;
    int c = threadIdx.x;
    __shared__ float xs[C][NB];
#pragma unroll
    for (int i = 0; i < NB; i++)
        xs[c][i] = x[(size_t)(nb + i) * C + c];
    __syncthreads();
    float acc[NB];
#pragma unroll
    for (int i = 0; i < NB; i++) acc[i] = 0.f;
#pragma unroll 4
    for (int k = 0; k < C; k++) {
        float w = W[k * C + c];
        const float4 a0 = *(const float4*)&xs[k][0];
        const float4 a1 = *(const float4*)&xs[k][4];
        acc[0] = fmaf(a0.x, w, acc[0]);  acc[1] = fmaf(a0.y, w, acc[1]);
        acc[2] = fmaf(a0.z, w, acc[2]);  acc[3] = fmaf(a0.w, w, acc[3]);
        acc[4] = fmaf(a1.x, w, acc[4]);  acc[5] = fmaf(a1.y, w, acc[5]);
        acc[6] = fmaf(a1.z, w, acc[6]);  acc[7] = fmaf(a1.w, w, acc[7]);
    }
    // h -> fp16: pair channels (c, c+1) via shfl, even lanes store half2
#pragma unroll
    for (int i = 0; i < NB; i++) {
        float vn = __shfl_down_sync(0xffffffffu, acc[i], 1);
        if ((c & 1) == 0)
            g_h16[(size_t)(nb + i) * CH2 + (c >> 1)] = __floats2half2_rn(acc[i], vn);
    }

    float as = a_src[c], ad = a_dst[c];
    __shared__ float rs[NB][4], rd[NB][4];
    int lane = c & 31, wp = c >> 5;
#pragma unroll
    for (int i = 0; i < NB; i++) {
        float ps = acc[i] * as;
        float pd = acc[i] * ad;
#pragma unroll
        for (int o = 16; o > 0; o >>= 1) {
            ps += __shfl_down_sync(0xffffffffu, ps, o);
            pd += __shfl_down_sync(0xffffffffu, pd, o);
        }
        if (lane == 0) { rs[i][wp] = ps; rd[i][wp] = pd; }
    }
    __syncthreads();
    if (c < NB) {
        g_es[nb + c] = rs[c][0] + rs[c][1] + rs[c][2] + rs[c][3];
        g_ed[nb + c] = rd[c][0] + rd[c][1] + rd[c][2] + rd[c][3];
    }
}

// ---- fused softmax + aggregation: 1 warp per node, fp16 h rows ----
__global__ void k_gather(const float* __restrict__ b_gat, float* __restrict__ zout) {
    int wp = threadIdx.x >> 5, lane = threadIdx.x & 31;
    int n = blockIdx.x * 4 + wp;
    int off = g_off[n];
    int deg = g_off[n + 1] - off;
    float edn = g_ed[n];

    float mt = NEG_INF, st = 0.f;
    for (int j = lane; j < deg; j += 32) {
        float l = lrelu(g_es[g_adj[off + j]] + edn);
        if (l > mt) { st *= __expf(mt - l); mt = l; }
        st += __expf(l - mt);
    }
#pragma unroll
    for (int o = 16; o > 0; o >>= 1) {
        float mo = __shfl_xor_sync(0xffffffffu, mt, o);
        float so = __shfl_xor_sync(0xffffffffu, st, o);
        float pm = fmaxf(mt, mo);
        float a = (mt > NEG_INF) ? st * __expf(mt - pm) : 0.f;
        float b = (mo > NEG_INF) ? so * __expf(mo - pm) : 0.f;
        mt = pm; st = a + b;
    }
    float inv = 1.f / st;

    float4 acc = make_float4(0.f, 0.f, 0.f, 0.f);
    for (int base = 0; base < deg; base += 32) {
        int j = base + lane;
        int sj = 0; float cj = 0.f;
        if (j < deg) {
            sj = g_adj[off + j];
            cj = __expf(lrelu(g_es[sj] + edn) - mt);
        }
        int lim = min(32, deg - base);
#pragma unroll 4
        for (int it = 0; it < lim; it++) {
            int s    = __shfl_sync(0xffffffffu, sj, it);
            float cf = __shfl_sync(0xffffffffu, cj, it);
            uint2 u = *(const uint2*)(g_h16 + (size_t)s * CH2 + lane * 2);
            float2 f0 = __half22float2(*(__half2*)&u.x);
            float2 f1 = __half22float2(*(__half2*)&u.y);
            acc.x = fmaf(cf, f0.x, acc.x);
            acc.y = fmaf(cf, f0.y, acc.y);
            acc.z = fmaf(cf, f1.x, acc.z);
            acc.w = fmaf(cf, f1.y, acc.w);
        }
    }
    float4 bg = *(const float4*)(b_gat + lane * 4);
    float4 o4 = make_float4(acc.x * inv + bg.x, acc.y * inv + bg.y,
                            acc.z * inv + bg.z, acc.w * inv + bg.w);
    *(float4*)(zout + (size_t)n * C + lane * 4) = o4;
}

// ---- persistent TC decode: recon = tanh(z @ Wd + bd) ----
__global__ void __launch_bounds__(DEC_THREADS) k_decode(
        const float* __restrict__ Wd, const float* __restrict__ bd,
        float* __restrict__ out) {
    extern __shared__ float sm[];
    float* Ws = sm;
    float* Zs = sm + 128 * AS_STRIDE;
    int tid = threadIdx.x;

    for (int i = tid; i < C * C; i += DEC_THREADS) {
        int k = i >> 7, n = i & 127;
        Ws[k * AS_STRIDE + n] = __uint_as_float(tf32_of(Wd[k * C + n]));
    }

    const float* z = out + (size_t)N_NODES * C;
    int w = tid >> 5, lane = tid & 31;
    int g = lane >> 2, q = lane & 3;
    int wr = w & 3;
    int wn = (w >> 2) * 64;

    for (int t = blockIdx.x; t < N_TILES; t += DEC_BLKS) {
        int m0 = t * 64;
        __syncthreads();
        for (int i = tid; i < 64 * C; i += DEC_THREADS) {
            int r = i >> 7, k = i & 127;
            int row = m0 + r;
            float v = (row < N_NODES) ? z[(size_t)row * C + k] : 0.f;
            Zs[r * AS_STRIDE + k] = __uint_as_float(tf32_of(v));
        }
        __syncthreads();

        float c0[8], c1[8], c2[8], c3[8];
#pragma unroll
        for (int j = 0; j < 8; j++) { c0[j] = 0.f; c1[j] = 0.f; c2[j] = 0.f; c3[j] = 0.f; }

        const float* Ar0 = Zs + (wr * 16 + g) * AS_STRIDE;
        const float* Ar1 = Ar0 + 8 * AS_STRIDE;
#pragma unroll 4
        for (int ks = 0; ks < 16; ks++) {
            int k0 = ks * 8;
            unsigned a0 = __float_as_uint(Ar0[k0 + q]);
            unsigned a1 = __float_as_uint(Ar1[k0 + q]);
            unsigned a2 = __float_as_uint(Ar0[k0 + q + 4]);
            unsigned a3 = __float_as_uint(Ar1[k0 + q + 4]);
            const float* Wk0 = Ws + (k0 + q) * AS_STRIDE + wn + g;
            const float* Wk1 = Wk0 + 4 * AS_STRIDE;
#pragma unroll
            for (int j = 0; j < 8; j++) {
                unsigned b0 = __float_as_uint(Wk0[j * 8]);
                unsigned b1 = __float_as_uint(Wk1[j * 8]);
                MMA_TF32(c0[j], c1[j], c2[j], c3[j], a0, a1, a2, a3, b0, b1);
            }
        }

        int row0 = m0 + wr * 16 + g;
        int row1 = row0 + 8;
#pragma unroll
        for (int j = 0; j < 8; j++) {
            int col = wn + j * 8 + 2 * q;
            float2 bv = *(const float2*)(bd + col);
            if (row0 < N_NODES)
                *(float2*)(out + (size_t)row0 * C + col) =
                    make_float2(tanhf(c0[j] + bv.x), tanhf(c1[j] + bv.y));
            if (row1 < N_NODES)
                *(float2*)(out + (size_t)row1 * C + col) =
                    make_float2(tanhf(c2[j] + bv.x), tanhf(c3[j] + bv.y));
        }
    }
}

extern "C" void kernel_launch(void* const* d_in, const int* in_sizes, int n_in,
                              void* d_out, int out_size) {
    const float* x     = (const float*)d_in[0];
    const int*   ei    = (const int*)d_in[1];     // int32 (JAX x64 off)
    const float* W     = (const float*)d_in[2];
    const float* a_src = (const float*)d_in[3];
    const float* a_dst = (const float*)d_in[4];
    const float* b_gat = (const float*)d_in[5];
    const float* Wd    = (const float*)d_in[6];
    const float* bd    = (const float*)d_in[7];
    float* out  = (float*)d_out;
    float* zout = out + (size_t)N_NODES * C;

    cudaFuncSetAttribute(k_decode, cudaFuncAttributeMaxDynamicSharedMemorySize, DEC_SMEM);

    k_zero<<<(N_NODES + 255) / 256, 256>>>();
    k_hist<<<(E_TOT + 255) / 256, 256>>>(ei);
    k_scan_fused<<<NBLK, 1024>>>();
    k_gemm_fill<<<GEMM_BLKS + FILL_BLKS, C>>>(x, W, a_src, a_dst, ei);
    k_gather<<<N_NODES / 4, 128>>>(b_gat, zout);
    k_decode<<<DEC_BLKS, DEC_THREADS, DEC_SMEM>>>(Wd, bd, out);
}

// round 16
// speedup vs baseline: 1.6331x; 1.0319x over previous
#include <cuda_runtime.h>
#include <cuda_fp16.h>
#include <cstdint>

#define N_NODES 50000
#define N_EDGES 1600000
#define C 128
#define CH2 (C / 2)
#define E_TOT (N_EDGES + N_NODES)
#define NEG_SLOPE 0.2f
#define NEG_INF (-1e30f)
#define NBLK 49              // ceil(50000/1024)
#define N_TILES 782          // ceil(50000/64)
#define TCB 148              // persistent TC blocks (gemm + decode)
#define FILL_BLKS 3223
#define DEC_THREADS 256
#define AS_STRIDE 132
#define DEC_SMEM ((128 + 64) * AS_STRIDE * 4)
#define GEMM_SMEM (DEC_SMEM + 2 * 128 * 4)

// -------- scratch (no device allocs allowed) --------
__device__ __half2 g_h16[(size_t)N_NODES * CH2];   // h in fp16 (gather feed)
__device__ float g_es[N_NODES];
__device__ float g_ed[N_NODES];
__device__ int   g_deg[N_NODES];
__device__ int   g_off[N_NODES + 1];
__device__ int   g_cursor[N_NODES];
__device__ int   g_adj[E_TOT];
__device__ int   g_bsumv[NBLK];
__device__ int   g_bflag[NBLK];

__device__ __forceinline__ float lrelu(float x) {
    return x > 0.f ? x : NEG_SLOPE * x;
}
__device__ __forceinline__ unsigned tf32_of(float f) {
    unsigned u;
    asm("cvt.rna.tf32.f32 %0, %1;" : "=r"(u) : "f"(f));
    return u;
}
#define MMA_TF32(c0,c1,c2,c3,a0,a1,a2,a3,b0,b1) \
    asm("mma.sync.aligned.m16n8k8.row.col.f32.tf32.tf32.f32 " \
        "{%0,%1,%2,%3}, {%4,%5,%6,%7}, {%8,%9}, {%0,%1,%2,%3};" \
        : "+f"(c0), "+f"(c1), "+f"(c2), "+f"(c3) \
        : "r"(a0), "r"(a1), "r"(a2), "r"(a3), "r"(b0), "r"(b1))

__global__ void k_zero() {
    int i = blockIdx.x * blockDim.x + threadIdx.x;
    if (i < N_NODES) g_deg[i] = 0;
    if (i < NBLK) g_bflag[i] = 0;
}

__global__ void k_hist(const int* __restrict__ ei) {
    int e = blockIdx.x * blockDim.x + threadIdx.x;
    if (e >= E_TOT) return;
    int d = (e < N_EDGES) ? ei[N_EDGES + e] : (e - N_EDGES);
    atomicAdd(&g_deg[d], 1);
}

// ---- fused scan (publish/poll; 49 blocks all wave-1 resident) ----
__global__ void k_scan_fused() {
    int b = blockIdx.x, tid = threadIdx.x;
    int idx = b * 1024 + tid;
    int v = (idx < N_NODES) ? g_deg[idx] : 0;
    int lane = tid & 31, wp = tid >> 5;
    int val = v;
#pragma unroll
    for (int o = 1; o < 32; o <<= 1) {
        int t = __shfl_up_sync(0xffffffffu, val, o);
        if (lane >= o) val += t;
    }
    __shared__ int wsum[32];
    if (lane == 31) wsum[wp] = val;
    __syncthreads();
    if (wp == 0) {
        int s = wsum[lane];
#pragma unroll
        for (int o = 1; o < 32; o <<= 1) {
            int t = __shfl_up_sync(0xffffffffu, s, o);
            if (lane >= o) s += t;
        }
        wsum[lane] = s;
    }
    __syncthreads();
    int total = wsum[31];
    int incl = val + (wp ? wsum[wp - 1] : 0);

    if (tid == 0) {
        g_bsumv[b] = total;
        __threadfence();
        *(volatile int*)&g_bflag[b] = 1;
    }
    __shared__ int sv[64];
    __shared__ int s_carry;
    if (tid < b) {
        while (*(volatile int*)&g_bflag[tid] == 0) { }
        sv[tid] = *(volatile int*)&g_bsumv[tid];
    }
    __syncthreads();
    if (tid == 0) {
        int acc = 0;
        for (int i = 0; i < b; i++) acc += sv[i];
        s_carry = acc;
    }
    __syncthreads();
    int carry = s_carry;
    if (idx < N_NODES) {
        int o = (incl - v) + carry;
        g_off[idx] = o;
        g_cursor[idx] = o;
    }
    if (b == NBLK - 1 && tid == 1023)
        g_off[N_NODES] = carry + total;
}

// ---- merged: persistent TC tf32 gemm1 (h fp16 + es/ed) + CSR fill ----
__global__ void __launch_bounds__(DEC_THREADS) k_gemm_fill(
        const float* __restrict__ x, const float* __restrict__ W,
        const float* __restrict__ a_src, const float* __restrict__ a_dst,
        const int* __restrict__ ei) {
    if (blockIdx.x >= TCB) {
        // -------- fill part --------
        int tid = (blockIdx.x - TCB) * DEC_THREADS + threadIdx.x;
        int stride = FILL_BLKS * DEC_THREADS;
        for (int e = tid; e < E_TOT; e += stride) {
            int s, d;
            if (e < N_EDGES) { s = ei[e]; d = ei[N_EDGES + e]; }
            else             { s = e - N_EDGES; d = s; }
            int pos = atomicAdd(&g_cursor[d], 1);
            g_adj[pos] = s;
        }
        return;
    }
    // -------- persistent TC GEMM part --------
    extern __shared__ float sm[];
    float* Ws = sm;                        // [128][AS_STRIDE] tf32 W
    float* Zs = sm + 128 * AS_STRIDE;      // [64][AS_STRIDE] tf32 x tile
    float* sm_es = sm + (128 + 64) * AS_STRIDE;   // [64][2]
    float* sm_ed = sm_es + 128;                    // [64][2]
    int tid = threadIdx.x;

    for (int i = tid; i < C * C; i += DEC_THREADS) {
        int k = i >> 7, n = i & 127;
        Ws[k * AS_STRIDE + n] = __uint_as_float(tf32_of(W[k * C + n]));
    }

    int w = tid >> 5, lane = tid & 31;
    int g = lane >> 2, q = lane & 3;
    int wr = w & 3;
    int hf = w >> 2;
    int wn = hf * 64;

    for (int t = blockIdx.x; t < N_TILES; t += TCB) {
        int m0 = t * 64;
        __syncthreads();   // Ws ready (iter 0); prior-iter smem reads done
        for (int i = tid; i < 64 * C; i += DEC_THREADS) {
            int r = i >> 7, k = i & 127;
            int row = m0 + r;
            float v = (row < N_NODES) ? x[(size_t)row * C + k] : 0.f;
            Zs[r * AS_STRIDE + k] = __uint_as_float(tf32_of(v));
        }
        __syncthreads();

        float c0[8], c1[8], c2[8], c3[8];
#pragma unroll
        for (int j = 0; j < 8; j++) { c0[j] = 0.f; c1[j] = 0.f; c2[j] = 0.f; c3[j] = 0.f; }

        const float* Ar0 = Zs + (wr * 16 + g) * AS_STRIDE;
        const float* Ar1 = Ar0 + 8 * AS_STRIDE;
#pragma unroll 4
        for (int ks = 0; ks < 16; ks++) {
            int k0 = ks * 8;
            unsigned a0 = __float_as_uint(Ar0[k0 + q]);
            unsigned a1 = __float_as_uint(Ar1[k0 + q]);
            unsigned a2 = __float_as_uint(Ar0[k0 + q + 4]);
            unsigned a3 = __float_as_uint(Ar1[k0 + q + 4]);
            const float* Wk0 = Ws + (k0 + q) * AS_STRIDE + wn + g;
            const float* Wk1 = Wk0 + 4 * AS_STRIDE;
#pragma unroll
            for (int j = 0; j < 8; j++) {
                unsigned b0 = __float_as_uint(Wk0[j * 8]);
                unsigned b1 = __float_as_uint(Wk1[j * 8]);
                MMA_TF32(c0[j], c1[j], c2[j], c3[j], a0, a1, a2, a3, b0, b1);
            }
        }

        // epilogue: fp16 h stores + es/ed partials
        int row0 = m0 + wr * 16 + g;
        int row1 = row0 + 8;
        float ps0 = 0.f, pd0 = 0.f, ps1 = 0.f, pd1 = 0.f;
#pragma unroll
        for (int j = 0; j < 8; j++) {
            int col = wn + j * 8 + 2 * q;
            float2 av = *(const float2*)(a_src + col);
            float2 dv = *(const float2*)(a_dst + col);
            ps0 += c0[j] * av.x + c1[j] * av.y;
            pd0 += c0[j] * dv.x + c1[j] * dv.y;
            ps1 += c2[j] * av.x + c3[j] * av.y;
            pd1 += c2[j] * dv.x + c3[j] * dv.y;
            int hcol = (wn >> 1) + j * 4 + q;
            if (row0 < N_NODES)
                g_h16[(size_t)row0 * CH2 + hcol] = __floats2half2_rn(c0[j], c1[j]);
            if (row1 < N_NODES)
                g_h16[(size_t)row1 * CH2 + hcol] = __floats2half2_rn(c2[j], c3[j]);
        }
#pragma unroll
        for (int o = 1; o < 4; o <<= 1) {
            ps0 += __shfl_xor_sync(0xffffffffu, ps0, o);
            pd0 += __shfl_xor_sync(0xffffffffu, pd0, o);
            ps1 += __shfl_xor_sync(0xffffffffu, ps1, o);
            pd1 += __shfl_xor_sync(0xffffffffu, pd1, o);
        }
        if (q == 0) {
            int r0 = wr * 16 + g, r1 = r0 + 8;
            sm_es[r0 * 2 + hf] = ps0;  sm_ed[r0 * 2 + hf] = pd0;
            sm_es[r1 * 2 + hf] = ps1;  sm_ed[r1 * 2 + hf] = pd1;
        }
        __syncthreads();
        if (tid < 64) {
            int row = m0 + tid;
            if (row < N_NODES) {
                g_es[row] = sm_es[tid * 2] + sm_es[tid * 2 + 1];
                g_ed[row] = sm_ed[tid * 2] + sm_ed[tid * 2 + 1];
            }
        }
    }
}

// ---- fused softmax + aggregation: 1 warp per node, fp16 h rows ----
__global__ void k_gather(const float* __restrict__ b_gat, float* __restrict__ zout) {
    int wp = threadIdx.x >> 5, lane = threadIdx.x & 31;
    int n = blockIdx.x * 4 + wp;
    int off = g_off[n];
    int deg = g_off[n + 1] - off;
    float edn = g_ed[n];

    float mt = NEG_INF, st = 0.f;
    for (int j = lane; j < deg; j += 32) {
        float l = lrelu(g_es[g_adj[off + j]] + edn);
        if (l > mt) { st *= __expf(mt - l); mt = l; }
        st += __expf(l - mt);
    }
#pragma unroll
    for (int o = 16; o > 0; o >>= 1) {
        float mo = __shfl_xor_sync(0xffffffffu, mt, o);
        float so = __shfl_xor_sync(0xffffffffu, st, o);
        float pm = fmaxf(mt, mo);
        float a = (mt > NEG_INF) ? st * __expf(mt - pm) : 0.f;
        float b = (mo > NEG_INF) ? so * __expf(mo - pm) : 0.f;
        mt = pm; st = a + b;
    }
    float inv = 1.f / st;

    float4 acc = make_float4(0.f, 0.f, 0.f, 0.f);
    for (int base = 0; base < deg; base += 32) {
        int j = base + lane;
        int sj = 0; float cj = 0.f;
        if (j < deg) {
            sj = g_adj[off + j];
            cj = __expf(lrelu(g_es[sj] + edn) - mt);
        }
        int lim = min(32, deg - base);
#pragma unroll 4
        for (int it = 0; it < lim; it++) {
            int s    = __shfl_sync(0xffffffffu, sj, it);
            float cf = __shfl_sync(0xffffffffu, cj, it);
            uint2 u = *(const uint2*)(g_h16 + (size_t)s * CH2 + lane * 2);
            float2 f0 = __half22float2(*(__half2*)&u.x);
            float2 f1 = __half22float2(*(__half2*)&u.y);
            acc.x = fmaf(cf, f0.x, acc.x);
            acc.y = fmaf(cf, f0.y, acc.y);
            acc.z = fmaf(cf, f1.x, acc.z);
            acc.w = fmaf(cf, f1.y, acc.w);
        }
    }
    float4 bg = *(const float4*)(b_gat + lane * 4);
    float4 o4 = make_float4(acc.x * inv + bg.x, acc.y * inv + bg.y,
                            acc.z * inv + bg.z, acc.w * inv + bg.w);
    *(float4*)(zout + (size_t)n * C + lane * 4) = o4;
}

// ---- persistent TC decode: recon = tanh(z @ Wd + bd) ----
__global__ void __launch_bounds__(DEC_THREADS) k_decode(
        const float* __restrict__ Wd, const float* __restrict__ bd,
        float* __restrict__ out) {
    extern __shared__ float sm[];
    float* Ws = sm;
    float* Zs = sm + 128 * AS_STRIDE;
    int tid = threadIdx.x;

    for (int i = tid; i < C * C; i += DEC_THREADS) {
        int k = i >> 7, n = i & 127;
        Ws[k * AS_STRIDE + n] = __uint_as_float(tf32_of(Wd[k * C + n]));
    }

    const float* z = out + (size_t)N_NODES * C;
    int w = tid >> 5, lane = tid & 31;
    int g = lane >> 2, q = lane & 3;
    int wr = w & 3;
    int wn = (w >> 2) * 64;

    for (int t = blockIdx.x; t < N_TILES; t += TCB) {
        int m0 = t * 64;
        __syncthreads();
        for (int i = tid; i < 64 * C; i += DEC_THREADS) {
            int r = i >> 7, k = i & 127;
            int row = m0 + r;
            float v = (row < N_NODES) ? z[(size_t)row * C + k] : 0.f;
            Zs[r * AS_STRIDE + k] = __uint_as_float(tf32_of(v));
        }
        __syncthreads();

        float c0[8], c1[8], c2[8], c3[8];
#pragma unroll
        for (int j = 0; j < 8; j++) { c0[j] = 0.f; c1[j] = 0.f; c2[j] = 0.f; c3[j] = 0.f; }

        const float* Ar0 = Zs + (wr * 16 + g) * AS_STRIDE;
        const float* Ar1 = Ar0 + 8 * AS_STRIDE;
#pragma unroll 4
        for (int ks = 0; ks < 16; ks++) {
            int k0 = ks * 8;
            unsigned a0 = __float_as_uint(Ar0[k0 + q]);
            unsigned a1 = __float_as_uint(Ar1[k0 + q]);
            unsigned a2 = __float_as_uint(Ar0[k0 + q + 4]);
            unsigned a3 = __float_as_uint(Ar1[k0 + q + 4]);
            const float* Wk0 = Ws + (k0 + q) * AS_STRIDE + wn + g;
            const float* Wk1 = Wk0 + 4 * AS_STRIDE;
#pragma unroll
            for (int j = 0; j < 8; j++) {
                unsigned b0 = __float_as_uint(Wk0[j * 8]);
                unsigned b1 = __float_as_uint(Wk1[j * 8]);
                MMA_TF32(c0[j], c1[j], c2[j], c3[j], a0, a1, a2, a3, b0, b1);
            }
        }

        int row0 = m0 + wr * 16 + g;
        int row1 = row0 + 8;
#pragma unroll
        for (int j = 0; j < 8; j++) {
            int col = wn + j * 8 + 2 * q;
            float2 bv = *(const float2*)(bd + col);
            if (row0 < N_NODES)
                *(float2*)(out + (size_t)row0 * C + col) =
                    make_float2(tanhf(c0[j] + bv.x), tanhf(c1[j] + bv.y));
            if (row1 < N_NODES)
                *(float2*)(out + (size_t)row1 * C + col) =
                    make_float2(tanhf(c2[j] + bv.x), tanhf(c3[j] + bv.y));
        }
    }
}

extern "C" void kernel_launch(void* const* d_in, const int* in_sizes, int n_in,
                              void* d_out, int out_size) {
    const float* x     = (const float*)d_in[0];
    const int*   ei    = (const int*)d_in[1];     // int32 (JAX x64 off)
    const float* W     = (const float*)d_in[2];
    const float* a_src = (const float*)d_in[3];
    const float* a_dst = (const float*)d_in[4];
    const float* b_gat = (const float*)d_in[5];
    const float* Wd    = (const float*)d_in[6];
    const float* bd    = (const float*)d_in[7];
    float* out  = (float*)d_out;
    float* zout = out + (size_t)N_NODES * C;

    cudaFuncSetAttribute(k_gemm_fill, cudaFuncAttributeMaxDynamicSharedMemorySize, GEMM_SMEM);
    cudaFuncSetAttribute(k_decode,   cudaFuncAttributeMaxDynamicSharedMemorySize, DEC_SMEM);

    k_zero<<<(N_NODES + 255) / 256, 256>>>();
    k_hist<<<(E_TOT + 255) / 256, 256>>>(ei);
    k_scan_fused<<<NBLK, 1024>>>();
    k_gemm_fill<<<TCB + FILL_BLKS, DEC_THREADS, GEMM_SMEM>>>(x, W, a_src, a_dst, ei);
    k_gather<<<N_NODES / 4, 128>>>(b_gat, zout);
    k_decode<<<TCB, DEC_THREADS, DEC_SMEM>>>(Wd, bd, out);
}

// round 17
// speedup vs baseline: 1.9594x; 1.1998x over previous
#include <cuda_runtime.h>
#include <cuda_fp16.h>
#include <cstdint>

#define N_NODES 50000
#define N_EDGES 1600000
#define C 128
#define CH2 (C / 2)
#define E_TOT (N_EDGES + N_NODES)
#define NEG_SLOPE 0.2f
#define NEG_INF (-1e30f)
#define NBLK 49              // ceil(50000/1024)
#define N_TILES 782          // ceil(50000/64)
#define TCB 296              // persistent TC blocks (2/SM)
#define FILL_BLKS 3223
#define DEC_THREADS 256
#define ZST 136              // smem stride in halves (272B -> banks 4g+q, conflict-free)
#define DEC_SMEM ((128 + 64) * ZST * 2)
#define GEMM_SMEM (DEC_SMEM + 2 * 128 * 4)

// -------- scratch (no device allocs allowed) --------
__device__ __half2 g_h16[(size_t)N_NODES * CH2];   // h in fp16 (gather feed)
__device__ float g_es[N_NODES];
__device__ float g_ed[N_NODES];
__device__ int   g_deg[N_NODES];
__device__ int   g_off[N_NODES + 1];
__device__ int   g_cursor[N_NODES];
__device__ int   g_adj[E_TOT];
__device__ int   g_bsumv[NBLK];
__device__ int   g_bflag[NBLK];

__device__ __forceinline__ float lrelu(float x) {
    return x > 0.f ? x : NEG_SLOPE * x;
}
#define MMA_F16(c0,c1,c2,c3,a0,a1,a2,a3,b0,b1) \
    asm("mma.sync.aligned.m16n8k16.row.col.f32.f16.f16.f32 " \
        "{%0,%1,%2,%3}, {%4,%5,%6,%7}, {%8,%9}, {%0,%1,%2,%3};" \
        : "+f"(c0), "+f"(c1), "+f"(c2), "+f"(c3) \
        : "r"(a0), "r"(a1), "r"(a2), "r"(a3), "r"(b0), "r"(b1))

__global__ void k_zero() {
    int i = blockIdx.x * blockDim.x + threadIdx.x;
    if (i < N_NODES) g_deg[i] = 0;
    if (i < NBLK) g_bflag[i] = 0;
}

__global__ void k_hist(const int* __restrict__ ei) {
    int e = blockIdx.x * blockDim.x + threadIdx.x;
    if (e >= E_TOT) return;
    int d = (e < N_EDGES) ? ei[N_EDGES + e] : (e - N_EDGES);
    atomicAdd(&g_deg[d], 1);
}

// ---- fused scan (publish/poll; 49 blocks all wave-1 resident) ----
__global__ void k_scan_fused() {
    int b = blockIdx.x, tid = threadIdx.x;
    int idx = b * 1024 + tid;
    int v = (idx < N_NODES) ? g_deg[idx] : 0;
    int lane = tid & 31, wp = tid >> 5;
    int val = v;
#pragma unroll
    for (int o = 1; o < 32; o <<= 1) {
        int t = __shfl_up_sync(0xffffffffu, val, o);
        if (lane >= o) val += t;
    }
    __shared__ int wsum[32];
    if (lane == 31) wsum[wp] = val;
    __syncthreads();
    if (wp == 0) {
        int s = wsum[lane];
#pragma unroll
        for (int o = 1; o < 32; o <<= 1) {
            int t = __shfl_up_sync(0xffffffffu, s, o);
            if (lane >= o) s += t;
        }
        wsum[lane] = s;
    }
    __syncthreads();
    int total = wsum[31];
    int incl = val + (wp ? wsum[wp - 1] : 0);

    if (tid == 0) {
        g_bsumv[b] = total;
        __threadfence();
        *(volatile int*)&g_bflag[b] = 1;
    }
    __shared__ int sv[64];
    __shared__ int s_carry;
    if (tid < b) {
        while (*(volatile int*)&g_bflag[tid] == 0) { }
        sv[tid] = *(volatile int*)&g_bsumv[tid];
    }
    __syncthreads();
    if (tid == 0) {
        int acc = 0;
        for (int i = 0; i < b; i++) acc += sv[i];
        s_carry = acc;
    }
    __syncthreads();
    int carry = s_carry;
    if (idx < N_NODES) {
        int o = (incl - v) + carry;
        g_off[idx] = o;
        g_cursor[idx] = o;
    }
    if (b == NBLK - 1 && tid == 1023)
        g_off[N_NODES] = carry + total;
}

// ---- merged: persistent fp16-MMA gemm1 (h fp16 + es/ed) + CSR fill ----
__global__ void __launch_bounds__(DEC_THREADS) k_gemm_fill(
        const float* __restrict__ x, const float* __restrict__ W,
        const float* __restrict__ a_src, const float* __restrict__ a_dst,
        const int* __restrict__ ei) {
    if (blockIdx.x >= TCB) {
        int tid = (blockIdx.x - TCB) * DEC_THREADS + threadIdx.x;
        int stride = FILL_BLKS * DEC_THREADS;
        for (int e = tid; e < E_TOT; e += stride) {
            int s, d;
            if (e < N_EDGES) { s = ei[e]; d = ei[N_EDGES + e]; }
            else             { s = e - N_EDGES; d = s; }
            int pos = atomicAdd(&g_cursor[d], 1);
            g_adj[pos] = s;
        }
        return;
    }
    extern __shared__ __half smh[];
    __half* Ws = smh;                  // [n:128][k:ZST]  (n-major for B fragments)
    __half* Zs = smh + 128 * ZST;      // [r:64][k:ZST]
    float* sm_es = (float*)(smh + (128 + 64) * ZST);   // [64][2]
    float* sm_ed = sm_es + 128;
    int tid = threadIdx.x;

    // stage W transposed to n-major fp16 (once per block)
    for (int i = tid; i < C * CH2; i += DEC_THREADS) {
        int n = i >> 6, kp = i & 63;
        int k = kp * 2;
        float w0 = W[k * C + n];
        float w1 = W[(k + 1) * C + n];
        *(__half2*)&Ws[n * ZST + k] = __floats2half2_rn(w0, w1);
    }

    int w = tid >> 5, lane = tid & 31;
    int g = lane >> 2, q = lane & 3;
    int wr = w & 3;
    int hf = w >> 2;
    int wn = hf * 64;

    for (int t = blockIdx.x; t < N_TILES; t += TCB) {
        int m0 = t * 64;
        __syncthreads();
        for (int i = tid; i < 64 * CH2; i += DEC_THREADS) {
            int r = i >> 6, kp = i & 63;
            int row = m0 + r;
            float2 v = (row < N_NODES) ? *(const float2*)(x + (size_t)row * C + kp * 2)
                                       : make_float2(0.f, 0.f);
            *(__half2*)&Zs[r * ZST + kp * 2] = __float22half2_rn(v);
        }
        __syncthreads();

        float c0[8], c1[8], c2[8], c3[8];
#pragma unroll
        for (int j = 0; j < 8; j++) { c0[j] = 0.f; c1[j] = 0.f; c2[j] = 0.f; c3[j] = 0.f; }

        const __half* Abase = Zs + (wr * 16 + g) * ZST + 2 * q;
        const __half* Bbase = Ws + (wn + g) * ZST + 2 * q;
#pragma unroll
        for (int ks = 0; ks < 8; ks++) {
            int k0 = ks * 16;
            unsigned a0 = *(const unsigned*)(Abase + k0);
            unsigned a1 = *(const unsigned*)(Abase + k0 + 8 * ZST);
            unsigned a2 = *(const unsigned*)(Abase + k0 + 8);
            unsigned a3 = *(const unsigned*)(Abase + k0 + 8 * ZST + 8);
#pragma unroll
            for (int j = 0; j < 8; j++) {
                unsigned b0 = *(const unsigned*)(Bbase + j * 8 * ZST + k0);
                unsigned b1 = *(const unsigned*)(Bbase + j * 8 * ZST + k0 + 8);
                MMA_F16(c0[j], c1[j], c2[j], c3[j], a0, a1, a2, a3, b0, b1);
            }
        }

        int row0 = m0 + wr * 16 + g;
        int row1 = row0 + 8;
        float ps0 = 0.f, pd0 = 0.f, ps1 = 0.f, pd1 = 0.f;
#pragma unroll
        for (int j = 0; j < 8; j++) {
            int col = wn + j * 8 + 2 * q;
            float2 av = *(const float2*)(a_src + col);
            float2 dv = *(const float2*)(a_dst + col);
            ps0 += c0[j] * av.x + c1[j] * av.y;
            pd0 += c0[j] * dv.x + c1[j] * dv.y;
            ps1 += c2[j] * av.x + c3[j] * av.y;
            pd1 += c2[j] * dv.x + c3[j] * dv.y;
            int hcol = (wn >> 1) + j * 4 + q;
            if (row0 < N_NODES)
                g_h16[(size_t)row0 * CH2 + hcol] = __floats2half2_rn(c0[j], c1[j]);
            if (row1 < N_NODES)
                g_h16[(size_t)row1 * CH2 + hcol] = __floats2half2_rn(c2[j], c3[j]);
        }
#pragma unroll
        for (int o = 1; o < 4; o <<= 1) {
            ps0 += __shfl_xor_sync(0xffffffffu, ps0, o);
            pd0 += __shfl_xor_sync(0xffffffffu, pd0, o);
            ps1 += __shfl_xor_sync(0xffffffffu, ps1, o);
            pd1 += __shfl_xor_sync(0xffffffffu, pd1, o);
        }
        if (q == 0) {
            int r0 = wr * 16 + g, r1 = r0 + 8;
            sm_es[r0 * 2 + hf] = ps0;  sm_ed[r0 * 2 + hf] = pd0;
            sm_es[r1 * 2 + hf] = ps1;  sm_ed[r1 * 2 + hf] = pd1;
        }
        __syncthreads();
        if (tid < 64) {
            int row = m0 + tid;
            if (row < N_NODES) {
                g_es[row] = sm_es[tid * 2] + sm_es[tid * 2 + 1];
                g_ed[row] = sm_ed[tid * 2] + sm_ed[tid * 2 + 1];
            }
        }
    }
}

// ---- fused softmax + aggregation: 1 warp per node, fp16 h rows ----
__global__ void k_gather(const float* __restrict__ b_gat, float* __restrict__ zout) {
    int wp = threadIdx.x >> 5, lane = threadIdx.x & 31;
    int n = blockIdx.x * 4 + wp;
    int off = g_off[n];
    int deg = g_off[n + 1] - off;
    float edn = g_ed[n];

    float mt = NEG_INF, st = 0.f;
    for (int j = lane; j < deg; j += 32) {
        float l = lrelu(g_es[g_adj[off + j]] + edn);
        if (l > mt) { st *= __expf(mt - l); mt = l; }
        st += __expf(l - mt);
    }
#pragma unroll
    for (int o = 16; o > 0; o >>= 1) {
        float mo = __shfl_xor_sync(0xffffffffu, mt, o);
        float so = __shfl_xor_sync(0xffffffffu, st, o);
        float pm = fmaxf(mt, mo);
        float a = (mt > NEG_INF) ? st * __expf(mt - pm) : 0.f;
        float b = (mo > NEG_INF) ? so * __expf(mo - pm) : 0.f;
        mt = pm; st = a + b;
    }
    float inv = 1.f / st;

    float4 acc = make_float4(0.f, 0.f, 0.f, 0.f);
    for (int base = 0; base < deg; base += 32) {
        int j = base + lane;
        int sj = 0; float cj = 0.f;
        if (j < deg) {
            sj = g_adj[off + j];
            cj = __expf(lrelu(g_es[sj] + edn) - mt);
        }
        int lim = min(32, deg - base);
#pragma unroll 4
        for (int it = 0; it < lim; it++) {
            int s    = __shfl_sync(0xffffffffu, sj, it);
            float cf = __shfl_sync(0xffffffffu, cj, it);
            uint2 u = *(const uint2*)(g_h16 + (size_t)s * CH2 + lane * 2);
            float2 f0 = __half22float2(*(__half2*)&u.x);
            float2 f1 = __half22float2(*(__half2*)&u.y);
            acc.x = fmaf(cf, f0.x, acc.x);
            acc.y = fmaf(cf, f0.y, acc.y);
            acc.z = fmaf(cf, f1.x, acc.z);
            acc.w = fmaf(cf, f1.y, acc.w);
        }
    }
    float4 bg = *(const float4*)(b_gat + lane * 4);
    float4 o4 = make_float4(acc.x * inv + bg.x, acc.y * inv + bg.y,
                            acc.z * inv + bg.z, acc.w * inv + bg.w);
    *(float4*)(zout + (size_t)n * C + lane * 4) = o4;
}

// ---- persistent fp16-MMA decode: recon = tanh(z @ Wd + bd) ----
__global__ void __launch_bounds__(DEC_THREADS) k_decode(
        const float* __restrict__ Wd, const float* __restrict__ bd,
        float* __restrict__ out) {
    extern __shared__ __half smh[];
    __half* Ws = smh;
    __half* Zs = smh + 128 * ZST;
    int tid = threadIdx.x;

    for (int i = tid; i < C * CH2; i += DEC_THREADS) {
        int n = i >> 6, kp = i & 63;
        int k = kp * 2;
        float w0 = Wd[k * C + n];
        float w1 = Wd[(k + 1) * C + n];
        *(__half2*)&Ws[n * ZST + k] = __floats2half2_rn(w0, w1);
    }

    const float* z = out + (size_t)N_NODES * C;
    int w = tid >> 5, lane = tid & 31;
    int g = lane >> 2, q = lane & 3;
    int wr = w & 3;
    int wn = (w >> 2) * 64;

    for (int t = blockIdx.x; t < N_TILES; t += TCB) {
        int m0 = t * 64;
        __syncthreads();
        for (int i = tid; i < 64 * CH2; i += DEC_THREADS) {
            int r = i >> 6, kp = i & 63;
            int row = m0 + r;
            float2 v = (row < N_NODES) ? *(const float2*)(z + (size_t)row * C + kp * 2)
                                       : make_float2(0.f, 0.f);
            *(__half2*)&Zs[r * ZST + kp * 2] = __float22half2_rn(v);
        }
        __syncthreads();

        float c0[8], c1[8], c2[8], c3[8];
#pragma unroll
        for (int j = 0; j < 8; j++) { c0[j] = 0.f; c1[j] = 0.f; c2[j] = 0.f; c3[j] = 0.f; }

        const __half* Abase = Zs + (wr * 16 + g) * ZST + 2 * q;
        const __half* Bbase = Ws + (wn + g) * ZST + 2 * q;
#pragma unroll
        for (int ks = 0; ks < 8; ks++) {
            int k0 = ks * 16;
            unsigned a0 = *(const unsigned*)(Abase + k0);
            unsigned a1 = *(const unsigned*)(Abase + k0 + 8 * ZST);
            unsigned a2 = *(const unsigned*)(Abase + k0 + 8);
            unsigned a3 = *(const unsigned*)(Abase + k0 + 8 * ZST + 8);
#pragma unroll
            for (int j = 0; j < 8; j++) {
                unsigned b0 = *(const unsigned*)(Bbase + j * 8 * ZST + k0);
                unsigned b1 = *(const unsigned*)(Bbase + j * 8 * ZST + k0 + 8);
                MMA_F16(c0[j], c1[j], c2[j], c3[j], a0, a1, a2, a3, b0, b1);
            }
        }

        int row0 = m0 + wr * 16 + g;
        int row1 = row0 + 8;
#pragma unroll
        for (int j = 0; j < 8; j++) {
            int col = wn + j * 8 + 2 * q;
            float2 bv = *(const float2*)(bd + col);
            if (row0 < N_NODES)
                *(float2*)(out + (size_t)row0 * C + col) =
                    make_float2(tanhf(c0[j] + bv.x), tanhf(c1[j] + bv.y));
            if (row1 < N_NODES)
                *(float2*)(out + (size_t)row1 * C + col) =
                    make_float2(tanhf(c2[j] + bv.x), tanhf(c3[j] + bv.y));
        }
    }
}

extern "C" void kernel_launch(void* const* d_in, const int* in_sizes, int n_in,
                              void* d_out, int out_size) {
    const float* x     = (const float*)d_in[0];
    const int*   ei    = (const int*)d_in[1];     // int32 (JAX x64 off)
    const float* W     = (const float*)d_in[2];
    const float* a_src = (const float*)d_in[3];
    const float* a_dst = (const float*)d_in[4];
    const float* b_gat = (const float*)d_in[5];
    const float* Wd    = (const float*)d_in[6];
    const float* bd    = (const float*)d_in[7];
    float* out  = (float*)d_out;
    float* zout = out + (size_t)N_NODES * C;

    cudaFuncSetAttribute(k_gemm_fill, cudaFuncAttributeMaxDynamicSharedMemorySize, GEMM_SMEM);
    cudaFuncSetAttribute(k_decode,   cudaFuncAttributeMaxDynamicSharedMemorySize, DEC_SMEM);

    k_zero<<<(N_NODES + 255) / 256, 256>>>();
    k_hist<<<(E_TOT + 255) / 256, 256>>>(ei);
    k_scan_fused<<<NBLK, 1024>>>();
    k_gemm_fill<<<TCB + FILL_BLKS, DEC_THREADS, GEMM_SMEM>>>(x, W, a_src, a_dst, ei);
    k_gather<<<N_NODES / 4, 128>>>(b_gat, zout);
    k_decode<<<TCB, DEC_THREADS, DEC_SMEM>>>(Wd, bd, out);
}